// round 16
// baseline (speedup 1.0000x reference)
#include <cuda_runtime.h>
#include <cuda_fp16.h>
#include <cstdint>

// GCN: 2x GraphConv (norm='both') + attention pooling + 3-layer MLP -> scalar.
//  - norm_s commutes out of conv1 -> gemm1 needs NO graph data; the bucket
//    fill runs as a grid-stride prologue INSIDE every gemm1 block, hiding its
//    atomic latency under the latency-bound HMMA GEMM (true overlap, unlike
//    the r9 block-split which ran wave-exclusive).
//  - agg80 applies ns[src] per edge via half2 HFMA2 (g_nsh table from k_ns).
//  - conv2 GEMM: split-fp16 (hi+lo) HMMA (validated r14, 20.7us, 4.7e-5).

#define N_MAX 100000
#define E_MAX 3200000
#define BCAP  128          // bucket capacity per node (17 sigma above mean 32)

// ---- scratch: static __device__ arrays (zero-initialized at module load) --
__device__ __align__(16) __half g_h1p[(size_t)N_MAX * 80]; // x@W1 (UNSCALED) fp16
__device__ __align__(16) float  g_h1 [(size_t)N_MAX * 80]; // relu(conv1) fp32
__device__ __align__(16) __half g_h2p[(size_t)N_MAX * 40]; // (h1*ns)@W2 fp16
__device__ __align__(16) __half g_h2 [(size_t)N_MAX * 40]; // relu(conv2) fp16
__device__ int      g_bucket[(size_t)N_MAX * BCAP];
__device__ int      g_cnt [N_MAX];   // in-degree (cursor); re-zeroed in k_attn
__device__ int      g_outc[N_MAX];   // out-degree;          re-zeroed in k_attn
__device__ uint32_t g_nsh [N_MAX];   // half2(ns,ns) per node (overwritten each launch)
__device__ __align__(16) float g_colsum[40];  // re-zeroed in k_mlp
__device__ __align__(16) float g_tvec [40];
__device__ __align__(16) float g_rep  [40];   // re-zeroed in k_mlp

// ------------------------------------------- FUSED: edge fill + conv1 GEMM
// Every block: (1) grid-stride slice of the bucket fill (int4 x edges),
//              (2) 128-row HMMA GEMM  g_h1p = fp16(in_feat @ W1)  (unscaled).
#define G1K 256
#define G1N 80
#define G1BM 128

__global__ void __launch_bounds__(256, 3)
k_fused(const float* __restrict__ A, const float* __restrict__ W,
        const int* __restrict__ src, const int* __restrict__ dst,
        int n, int e)
{
    __shared__ __half Wt[G1N][G1K + 8];   // 80 x 264 halves = 41.25 KB

    const int tid = threadIdx.x;

    // ---------------- edge-fill slice (overlaps with other blocks' GEMMs) --
    {
        int nthr = gridDim.x * 256;
        int gid  = blockIdx.x * 256 + tid;
        int q = e >> 2;
        for (int i = gid; i < q; i += nthr) {
            int4 s4 = __ldg((const int4*)src + i);
            int4 d4 = __ldg((const int4*)dst + i);
            atomicAdd(&g_outc[s4.x], 1); atomicAdd(&g_outc[s4.y], 1);
            atomicAdd(&g_outc[s4.z], 1); atomicAdd(&g_outc[s4.w], 1);
            int p;
            p = atomicAdd(&g_cnt[d4.x], 1); if (p < BCAP) g_bucket[(size_t)d4.x * BCAP + p] = s4.x;
            p = atomicAdd(&g_cnt[d4.y], 1); if (p < BCAP) g_bucket[(size_t)d4.y * BCAP + p] = s4.y;
            p = atomicAdd(&g_cnt[d4.z], 1); if (p < BCAP) g_bucket[(size_t)d4.z * BCAP + p] = s4.z;
            p = atomicAdd(&g_cnt[d4.w], 1); if (p < BCAP) g_bucket[(size_t)d4.w * BCAP + p] = s4.w;
        }
        int r = q * 4 + gid;
        if (gid < (e & 3) && r < e) {
            int s = src[r], d = dst[r];
            atomicAdd(&g_outc[s], 1);
            int p = atomicAdd(&g_cnt[d], 1);
            if (p < BCAP) g_bucket[(size_t)d * BCAP + p] = s;
        }
    }

    // ---------------- HMMA GEMM (no graph dependency) ----------------------
    for (int idx = tid; idx < G1K * G1N; idx += 256) {
        int kk = idx / G1N;
        int nn = idx % G1N;
        Wt[nn][kk] = __float2half(W[idx]);
    }
    __syncthreads();

    const int warp = tid >> 5;
    const int lane = tid & 31;
    const int ar   = lane >> 2;
    const int ac   = (lane & 3) * 2;
    const int r0 = blockIdx.x * G1BM + warp * 16 + ar;
    const int r1 = r0 + 8;
    const bool v0 = r0 < n, v1 = r1 < n;
    const float2* A0 = reinterpret_cast<const float2*>(A + (size_t)r0 * G1K);
    const float2* A1 = reinterpret_cast<const float2*>(A + (size_t)r1 * G1K);

    float acc[10][4];
    #pragma unroll
    for (int nj = 0; nj < 10; nj++)
        #pragma unroll
        for (int c = 0; c < 4; c++) acc[nj][c] = 0.f;

    #pragma unroll
    for (int ks = 0; ks < 16; ks++) {
        int kc = ks * 16 + ac;
        float2 x0 = v0 ? __ldg(A0 + (kc >> 1))       : make_float2(0.f, 0.f);
        float2 x1 = v0 ? __ldg(A0 + ((kc + 8) >> 1)) : make_float2(0.f, 0.f);
        float2 y0 = v1 ? __ldg(A1 + (kc >> 1))       : make_float2(0.f, 0.f);
        float2 y1 = v1 ? __ldg(A1 + ((kc + 8) >> 1)) : make_float2(0.f, 0.f);
        __half2 ha0 = __floats2half2_rn(x0.x, x0.y);
        __half2 ha1 = __floats2half2_rn(y0.x, y0.y);
        __half2 ha2 = __floats2half2_rn(x1.x, x1.y);
        __half2 ha3 = __floats2half2_rn(y1.x, y1.y);
        uint32_t a0 = *reinterpret_cast<uint32_t*>(&ha0);
        uint32_t a1 = *reinterpret_cast<uint32_t*>(&ha1);
        uint32_t a2 = *reinterpret_cast<uint32_t*>(&ha2);
        uint32_t a3 = *reinterpret_cast<uint32_t*>(&ha3);
        #pragma unroll
        for (int nj = 0; nj < 10; nj++) {
            uint32_t b0 = *reinterpret_cast<const uint32_t*>(&Wt[nj * 8 + ar][ks * 16 + ac    ]);
            uint32_t b1 = *reinterpret_cast<const uint32_t*>(&Wt[nj * 8 + ar][ks * 16 + ac + 8]);
            asm volatile(
                "mma.sync.aligned.m16n8k16.row.col.f32.f16.f16.f32 "
                "{%0,%1,%2,%3}, {%4,%5,%6,%7}, {%8,%9}, {%0,%1,%2,%3};"
                : "+f"(acc[nj][0]), "+f"(acc[nj][1]),
                  "+f"(acc[nj][2]), "+f"(acc[nj][3])
                : "r"(a0), "r"(a1), "r"(a2), "r"(a3), "r"(b0), "r"(b1));
        }
    }

    #pragma unroll
    for (int nj = 0; nj < 10; nj++) {
        int col = nj * 8 + ac;
        if (v0) {
            __half2 h = __floats2half2_rn(acc[nj][0], acc[nj][1]);
            *reinterpret_cast<uint32_t*>(g_h1p + (size_t)r0 * G1N + col) =
                *reinterpret_cast<uint32_t*>(&h);
        }
        if (v1) {
            __half2 h = __floats2half2_rn(acc[nj][2], acc[nj][3]);
            *reinterpret_cast<uint32_t*>(g_h1p + (size_t)r1 * G1N + col) =
                *reinterpret_cast<uint32_t*>(&h);
        }
    }
}

// ---------------------------------------------------------------- ns table
__global__ void k_ns(int n) {
    int i = blockIdx.x * blockDim.x + threadIdx.x;
    if (i < n) {
        float ns = rsqrtf((float)max(g_outc[i], 1));
        __half2 h = __float2half2_rn(ns);
        g_nsh[i] = *reinterpret_cast<uint32_t*>(&h);
    }
}

// ---------------------------------------------------------------- gather 1
// Warp per dst node, 20 active lanes. Chunked fp16 HFMA2 accumulation:
// acc_h += ns2[src] * h1p[src]; chunk of 8 flushed into fp32.
__global__ void __launch_bounds__(256)
k_agg80(const float* __restrict__ bias, int n)
{
    int gw   = (blockIdx.x * blockDim.x + threadIdx.x) >> 5;
    int lane = threadIdx.x & 31;
    if (gw >= n || lane >= 20) return;
    int cntr = g_cnt[gw];
    int cnt  = min(cntr, BCAP);
    float nd = rsqrtf((float)max(cntr, 1));
    const int* brow = g_bucket + (size_t)gw * BCAP;
    const uint2* base = reinterpret_cast<const uint2*>(g_h1p);
    float4 acc = make_float4(0.f, 0.f, 0.f, 0.f);

    int e = 0;
    while (e < cnt) {
        int lim = min(e + 8, cnt);
        __half2 h0 = __float2half2_rn(0.f);
        __half2 h1 = __float2half2_rn(0.f);
        for (; e < lim; e++) {
            int s = __ldg(&brow[e]);
            uint32_t nsh = __ldg(&g_nsh[s]);
            __half2 ns2 = *reinterpret_cast<__half2*>(&nsh);
            uint2 v = __ldg(base + (size_t)s * 20 + lane);
            h0 = __hfma2(*reinterpret_cast<__half2*>(&v.x), ns2, h0);
            h1 = __hfma2(*reinterpret_cast<__half2*>(&v.y), ns2, h1);
        }
        float2 f0 = __half22float2(h0);
        float2 f1 = __half22float2(h1);
        acc.x += f0.x; acc.y += f0.y; acc.z += f1.x; acc.w += f1.y;
    }

    float4 b = *reinterpret_cast<const float4*>(bias + lane * 4);
    float4 o;
    o.x = fmaxf(fmaf(acc.x, nd, b.x), 0.f);
    o.y = fmaxf(fmaf(acc.y, nd, b.y), 0.f);
    o.z = fmaxf(fmaf(acc.z, nd, b.z), 0.f);
    o.w = fmaxf(fmaf(acc.w, nd, b.w), 0.f);
    reinterpret_cast<float4*>(g_h1)[(size_t)gw * 20 + lane] = o;
}

// --------------------------------------------------- conv2 GEMM via split HMMA
// g_h2p[n,40](fp16) = ((g_h1 * ns[:,None])[n,80]) @ W2[80,40]
#define G2K 80
#define G2N 40
#define G2BM 128

__device__ __forceinline__ void split2(float x, float y, uint32_t& hi, uint32_t& lo) {
    __half hx = __float2half_rn(x);
    __half hy = __float2half_rn(y);
    __half lx = __float2half_rn(x - __half2float(hx));
    __half ly = __float2half_rn(y - __half2float(hy));
    __half2 h = __halves2half2(hx, hy);
    __half2 l = __halves2half2(lx, ly);
    hi = *reinterpret_cast<uint32_t*>(&h);
    lo = *reinterpret_cast<uint32_t*>(&l);
}

#define MMA16816(ACC, A0, A1, A2, A3, B0, B1)                                 \
    asm volatile(                                                             \
        "mma.sync.aligned.m16n8k16.row.col.f32.f16.f16.f32 "                  \
        "{%0,%1,%2,%3}, {%4,%5,%6,%7}, {%8,%9}, {%0,%1,%2,%3};"               \
        : "+f"((ACC)[0]), "+f"((ACC)[1]), "+f"((ACC)[2]), "+f"((ACC)[3])      \
        : "r"(A0), "r"(A1), "r"(A2), "r"(A3), "r"(B0), "r"(B1))

__global__ void __launch_bounds__(256)
k_gemm2_hmma(const float* __restrict__ W, int n)
{
    __shared__ __half Wh[G2N][G2K + 8];   // 7 KB
    __shared__ __half Wl[G2N][G2K + 8];   // 7 KB

    const int tid  = threadIdx.x;
    const int warp = tid >> 5;
    const int lane = tid & 31;
    const int ar   = lane >> 2;
    const int ac   = (lane & 3) * 2;

    for (int idx = tid; idx < G2K * G2N; idx += 256) {
        int kk = idx / G2N;
        int nn = idx % G2N;
        float w = W[idx];
        __half h = __float2half_rn(w);
        Wh[nn][kk] = h;
        Wl[nn][kk] = __float2half_rn(w - __half2float(h));
    }
    __syncthreads();

    const int r0 = blockIdx.x * G2BM + warp * 16 + ar;
    const int r1 = r0 + 8;
    const bool v0 = r0 < n, v1 = r1 < n;
    const float ns0 = v0 ? rsqrtf((float)max(g_outc[r0], 1)) : 0.f;
    const float ns1 = v1 ? rsqrtf((float)max(g_outc[r1], 1)) : 0.f;
    const float2* A0 = reinterpret_cast<const float2*>(g_h1 + (size_t)r0 * G2K);
    const float2* A1 = reinterpret_cast<const float2*>(g_h1 + (size_t)r1 * G2K);

    float acc[5][4];
    #pragma unroll
    for (int nj = 0; nj < 5; nj++)
        #pragma unroll
        for (int c = 0; c < 4; c++) acc[nj][c] = 0.f;

    #pragma unroll
    for (int ks = 0; ks < 5; ks++) {
        int kc = ks * 16 + ac;
        float2 x0 = v0 ? __ldg(A0 + (kc >> 1))       : make_float2(0.f, 0.f);
        float2 x1 = v0 ? __ldg(A0 + ((kc + 8) >> 1)) : make_float2(0.f, 0.f);
        float2 y0 = v1 ? __ldg(A1 + (kc >> 1))       : make_float2(0.f, 0.f);
        float2 y1 = v1 ? __ldg(A1 + ((kc + 8) >> 1)) : make_float2(0.f, 0.f);
        uint32_t ah[4], al[4];
        split2(x0.x * ns0, x0.y * ns0, ah[0], al[0]);
        split2(y0.x * ns1, y0.y * ns1, ah[1], al[1]);
        split2(x1.x * ns0, x1.y * ns0, ah[2], al[2]);
        split2(y1.x * ns1, y1.y * ns1, ah[3], al[3]);
        #pragma unroll
        for (int nj = 0; nj < 5; nj++) {
            uint32_t bh0 = *reinterpret_cast<const uint32_t*>(&Wh[nj * 8 + ar][ks * 16 + ac    ]);
            uint32_t bh1 = *reinterpret_cast<const uint32_t*>(&Wh[nj * 8 + ar][ks * 16 + ac + 8]);
            uint32_t bl0 = *reinterpret_cast<const uint32_t*>(&Wl[nj * 8 + ar][ks * 16 + ac    ]);
            uint32_t bl1 = *reinterpret_cast<const uint32_t*>(&Wl[nj * 8 + ar][ks * 16 + ac + 8]);
            MMA16816(acc[nj], ah[0], ah[1], ah[2], ah[3], bh0, bh1);
            MMA16816(acc[nj], ah[0], ah[1], ah[2], ah[3], bl0, bl1);
            MMA16816(acc[nj], al[0], al[1], al[2], al[3], bh0, bh1);
        }
    }

    #pragma unroll
    for (int nj = 0; nj < 5; nj++) {
        int col = nj * 8 + ac;
        if (v0) {
            __half2 h = __floats2half2_rn(acc[nj][0], acc[nj][1]);
            *reinterpret_cast<uint32_t*>(g_h2p + (size_t)r0 * G2N + col) =
                *reinterpret_cast<uint32_t*>(&h);
        }
        if (v1) {
            __half2 h = __floats2half2_rn(acc[nj][2], acc[nj][3]);
            *reinterpret_cast<uint32_t*>(g_h2p + (size_t)r1 * G2N + col) =
                *reinterpret_cast<uint32_t*>(&h);
        }
    }
}

// ---------------------------------------------------------------- gather 2
// Half-warp per node, 10 active lanes; chunked fp16 accumulation; nd inline.
__global__ void __launch_bounds__(256)
k_agg40(const float* __restrict__ bias, int n)
{
    __shared__ float scol[40];
    int tid  = threadIdx.x;
    int gh   = (blockIdx.x * blockDim.x + tid) >> 4;
    int lane = tid & 15;
    if (tid < 40) scol[tid] = 0.f;
    __syncthreads();

    bool active = (gh < n) && (lane < 10);
    if (active) {
        int cntr = g_cnt[gh];
        int cnt  = min(cntr, BCAP);
        float nd = rsqrtf((float)max(cntr, 1));
        const int* brow = g_bucket + (size_t)gh * BCAP;
        const uint2* base = reinterpret_cast<const uint2*>(g_h2p);
        float4 acc = make_float4(0.f, 0.f, 0.f, 0.f);

        int e = 0;
        while (e < cnt) {
            int lim = min(e + 8, cnt);
            __half2 h0 = __float2half2_rn(0.f);
            __half2 h1 = __float2half2_rn(0.f);
            for (; e < lim; e++) {
                int s = __ldg(&brow[e]);
                uint2 v = __ldg(base + (size_t)s * 10 + lane);
                h0 = __hadd2(h0, *reinterpret_cast<__half2*>(&v.x));
                h1 = __hadd2(h1, *reinterpret_cast<__half2*>(&v.y));
            }
            float2 f0 = __half22float2(h0);
            float2 f1 = __half22float2(h1);
            acc.x += f0.x; acc.y += f0.y; acc.z += f1.x; acc.w += f1.y;
        }

        float4 b = *reinterpret_cast<const float4*>(bias + lane * 4);
        float4 o;
        o.x = fmaxf(fmaf(acc.x, nd, b.x), 0.f);
        o.y = fmaxf(fmaf(acc.y, nd, b.y), 0.f);
        o.z = fmaxf(fmaf(acc.z, nd, b.z), 0.f);
        o.w = fmaxf(fmaf(acc.w, nd, b.w), 0.f);
        uint2 hv;
        __half2 h0 = __floats2half2_rn(o.x, o.y);
        __half2 h1 = __floats2half2_rn(o.z, o.w);
        hv.x = *reinterpret_cast<uint32_t*>(&h0);
        hv.y = *reinterpret_cast<uint32_t*>(&h1);
        reinterpret_cast<uint2*>(g_h2)[(size_t)gh * 10 + lane] = hv;
        atomicAdd(&scol[lane * 4 + 0], o.x);
        atomicAdd(&scol[lane * 4 + 1], o.y);
        atomicAdd(&scol[lane * 4 + 2], o.z);
        atomicAdd(&scol[lane * 4 + 3], o.w);
    }
    __syncthreads();
    if (tid < 40) atomicAdd(&g_colsum[tid], scol[tid]);
}

// ---------------------------------------------------------------- context vec
__global__ void k_ctx(const float* __restrict__ Wa, int n) {
    int j = threadIdx.x;
    if (j < 40) {
        float inv = 1.f / (float)n;
        float gc = 0.f;
        for (int k = 0; k < 40; k++) gc += (g_colsum[k] * inv) * Wa[k * 40 + j];
        g_tvec[j] = tanhf(gc);
    }
}

// --------------------------------------- fused scores + weighted reduction
// Also re-zeroes g_cnt/g_outc for the next graph replay.
__global__ void __launch_bounds__(256)
k_attn(int n)
{
    __shared__ float sacc[40];
    int tid    = threadIdx.x;
    int lane   = tid & 15;
    int grp    = (blockIdx.x * blockDim.x + tid) >> 4;
    int ngrp   = (gridDim.x * blockDim.x) >> 4;
    bool active = lane < 10;
    if (tid < 40) sacc[tid] = 0.f;
    __syncthreads();

    float4 tv = active ? reinterpret_cast<const float4*>(g_tvec)[lane]
                       : make_float4(0.f, 0.f, 0.f, 0.f);
    float4 facc = make_float4(0.f, 0.f, 0.f, 0.f);
    const uint2* base = reinterpret_cast<const uint2*>(g_h2);

    for (int i = grp; i < n; i += ngrp) {
        float4 v = make_float4(0.f, 0.f, 0.f, 0.f);
        if (active) {
            uint2 hv = __ldg(base + (size_t)i * 10 + lane);
            float2 f0 = __half22float2(*reinterpret_cast<__half2*>(&hv.x));
            float2 f1 = __half22float2(*reinterpret_cast<__half2*>(&hv.y));
            v = make_float4(f0.x, f0.y, f1.x, f1.y);
        }
        float d = v.x * tv.x + v.y * tv.y + v.z * tv.z + v.w * tv.w;
        #pragma unroll
        for (int o = 8; o >= 1; o >>= 1)
            d += __shfl_down_sync(0xffffffffu, d, o, 16);
        d = __shfl_sync(0xffffffffu, d, 0, 16);
        float s = 1.f / (1.f + expf(-d));
        facc.x = fmaf(s, v.x, facc.x);
        facc.y = fmaf(s, v.y, facc.y);
        facc.z = fmaf(s, v.z, facc.z);
        facc.w = fmaf(s, v.w, facc.w);
    }
    if (active) {
        atomicAdd(&sacc[lane * 4 + 0], facc.x);
        atomicAdd(&sacc[lane * 4 + 1], facc.y);
        atomicAdd(&sacc[lane * 4 + 2], facc.z);
        atomicAdd(&sacc[lane * 4 + 3], facc.w);
    }
    __syncthreads();
    if (tid < 40) atomicAdd(&g_rep[tid], sacc[tid]);

    // reset degree counters for next replay (agg40 was the last reader)
    int gi = blockIdx.x * blockDim.x + tid;
    if (gi < n) { g_cnt[gi] = 0; g_outc[gi] = 0; }
}

// ---------------------------------------------------------------- final MLP
// Also re-zeroes g_colsum/g_rep for the next replay.
__global__ void k_mlp(const float* __restrict__ Wm1, const float* __restrict__ bm1,
                      const float* __restrict__ Wm2, const float* __restrict__ bm2,
                      const float* __restrict__ Wm3, const float* __restrict__ bm3,
                      float* __restrict__ out)
{
    __shared__ float g1s[30], g2s[10];
    int j = threadIdx.x;   // blockDim = 32
    if (j < 30) {
        float s = bm1[j];
        for (int k = 0; k < 40; k++) s += g_rep[k] * Wm1[k * 30 + j];
        g1s[j] = fmaxf(s, 0.f);
    }
    __syncthreads();
    if (j < 10) {
        float s = bm2[j];
        for (int k = 0; k < 30; k++) s += g1s[k] * Wm2[k * 10 + j];
        g2s[j] = fmaxf(s, 0.f);
    }
    __syncthreads();
    if (j == 0) {
        float s = bm3[0];
        for (int k = 0; k < 10; k++) s += g2s[k] * Wm3[k];
        out[0] = s;
    }
    for (int t = j; t < 40; t += 32) { g_colsum[t] = 0.f; g_rep[t] = 0.f; }
}

// ---------------------------------------------------------------- launch
extern "C" void kernel_launch(void* const* d_in, const int* in_sizes, int n_in,
                              void* d_out, int out_size)
{
    const float* in_feat = (const float*)d_in[0];
    const int*   src     = (const int*)  d_in[1];
    const int*   dst     = (const int*)  d_in[2];
    const float* W1      = (const float*)d_in[3];
    const float* b1      = (const float*)d_in[4];
    const float* W2      = (const float*)d_in[5];
    const float* b2      = (const float*)d_in[6];
    const float* Wa      = (const float*)d_in[7];
    const float* Wm1     = (const float*)d_in[8];
    const float* bm1     = (const float*)d_in[9];
    const float* Wm2     = (const float*)d_in[10];
    const float* bm2     = (const float*)d_in[11];
    const float* Wm3     = (const float*)d_in[12];
    const float* bm3     = (const float*)d_in[13];
    float* out = (float*)d_out;

    const int n = in_sizes[0] / 256;   // 100000
    const int e = in_sizes[1];         // 3200000

    const int nb_n = (n + 255) / 256;

    k_fused<<<(n + 127) / 128, 256>>>(in_feat, W1, src, dst, n, e);
    k_ns   <<<nb_n, 256>>>(n);

    k_agg80<<<(n + 7) / 8, 256>>>(b1, n);

    k_gemm2_hmma<<<(n + 127) / 128, 256>>>(W2, n);
    k_agg40<<<(n + 15) / 16, 256>>>(b2, n);

    k_ctx <<<1, 64>>>(Wa, n);
    k_attn<<<391, 256>>>(n);

    k_mlp<<<1, 32>>>(Wm1, bm1, Wm2, bm2, Wm3, bm3, out);
}